// round 11
// baseline (speedup 1.0000x reference)
#include <cuda_runtime.h>
#include <cuda_fp16.h>
#include <cstdint>

#define N_NODES 10000
#define N_EDGES 320000
#define DIM_IN  128
#define DIM_H   256
#define DIM_C   32
#define DIM_OUT 64
#define CAP     128
#define BMPW    313   // ceil(10000/32)
#define NQV     320   // v(256) | q(32) | k(32)

// ---------------- scratch (device globals) ------------------------------------
__device__ int    g_cnt[N_NODES];
__device__ int    g_adj[N_NODES * CAP];
__device__ __half g_x16  [(size_t)N_NODES * DIM_IN];
__device__ __half g_win16[DIM_IN * DIM_H];
__device__ __half g_wqkv16[DIM_H * NQV];                 // [Wv | Wq | Wk]
__device__ __half g_w116 [2 * DIM_H * DIM_H];
__device__ __half g_w216 [DIM_H * DIM_OUT];
__device__ __half g_comb16[(size_t)N_NODES * 2 * DIM_H]; // [h | comm], ld=512
__device__ __half g_qv16 [(size_t)N_NODES * NQV];        // [v | q | k], ld=320
__device__ float  g_bqkv[NQV];

// ---------------- prep: zero counts, convert x + weights to fp16 ----------------
__global__ void prep_kernel(const float* __restrict__ x,
                            const float* __restrict__ W_in,
                            const float* __restrict__ Wq, const float* __restrict__ bq,
                            const float* __restrict__ Wk, const float* __restrict__ bk,
                            const float* __restrict__ Wv, const float* __restrict__ bv,
                            const float* __restrict__ W1,
                            const float* __restrict__ W2) {
    int g = blockIdx.x * blockDim.x + threadIdx.x;
    int stride = gridDim.x * blockDim.x;
    for (int i = g; i < N_NODES * DIM_IN; i += stride) g_x16[i] = __float2half_rn(x[i]);
    for (int i = g; i < DIM_IN * DIM_H;  i += stride) g_win16[i] = __float2half_rn(W_in[i]);
    for (int i = g; i < 2 * DIM_H * DIM_H; i += stride) g_w116[i] = __float2half_rn(W1[i]);
    for (int i = g; i < DIM_H * DIM_OUT; i += stride) g_w216[i] = __float2half_rn(W2[i]);
    for (int i = g; i < DIM_H * NQV; i += stride) {
        int r = i / NQV, c = i % NQV;
        float w;
        if (c < 256)      w = Wv[r * 256 + c];
        else if (c < 288) w = Wq[r * 32 + (c - 256)];
        else              w = Wk[r * 32 + (c - 288)];
        g_wqkv16[i] = __float2half_rn(w);
    }
    for (int i = g; i < NQV; i += stride)
        g_bqkv[i] = (i < 256) ? bv[i] : (i < 288 ? bq[i - 256] : bk[i - 288]);
    for (int i = g; i < N_NODES; i += stride) g_cnt[i] = 0;
}

// ---------------- adjacency: append (dups deduped later in attn) ----------------
__global__ void insert_kernel(const int* __restrict__ ei) {
    int e = blockIdx.x * blockDim.x + threadIdx.x;
    if (e >= N_EDGES) return;
    int i = ei[e];
    int j = ei[N_EDGES + e];
    int pos = atomicAdd(&g_cnt[i], 1);
    if (pos < CAP) g_adj[i * CAP + pos] = j;
}

// ---------------- shared GEMM machinery ------------------------------------------
// 256 threads = 8 warps (4 along M x 2 along N); CTA tile 64 x 64 x 32.
#define BK 32
#define ASTR 40    // As row stride (halves): conflict-free ldmatrix
#define BSTR 72    // Bs row stride (halves)
#define HSTR 264   // smem h/t buffer row stride (halves): 264/8=33, 33%8=1 -> cf
#define STAGES 3

// smem layout (halves): As | Bs | Hs
#define AS_OFF 0
#define BS_OFF (STAGES * 64 * ASTR)                  // 7680
#define HS_OFF (BS_OFF + STAGES * BK * BSTR)         // 14592
#define SMEM_HALVES (HS_OFF + 64 * HSTR)             // 31488
#define SMEM_BYTES (SMEM_HALVES * 2)                 // 62976

__device__ __forceinline__ void ldsm_x4(uint32_t* r, uint32_t addr) {
    asm volatile("ldmatrix.sync.aligned.m8n8.x4.shared.b16 {%0,%1,%2,%3}, [%4];"
        : "=r"(r[0]), "=r"(r[1]), "=r"(r[2]), "=r"(r[3]) : "r"(addr));
}
__device__ __forceinline__ void ldsm_x4_t(uint32_t* r, uint32_t addr) {
    asm volatile("ldmatrix.sync.aligned.m8n8.x4.trans.shared.b16 {%0,%1,%2,%3}, [%4];"
        : "=r"(r[0]), "=r"(r[1]), "=r"(r[2]), "=r"(r[3]) : "r"(addr));
}
__device__ __forceinline__ void mma_f16(float* d, const uint32_t* a, const uint32_t* b) {
    asm volatile("mma.sync.aligned.m16n8k16.row.col.f32.f16.f16.f32 "
        "{%0,%1,%2,%3}, {%4,%5,%6,%7}, {%8,%9}, {%0,%1,%2,%3};"
        : "+f"(d[0]), "+f"(d[1]), "+f"(d[2]), "+f"(d[3])
        : "r"(a[0]), "r"(a[1]), "r"(a[2]), "r"(a[3]), "r"(b[0]), "r"(b[1]));
}
__device__ __forceinline__ void cp16(uint32_t dst, const void* src, int src_bytes) {
    asm volatile("cp.async.ca.shared.global [%0], [%1], 16, %2;"
        :: "r"(dst), "l"(src), "r"(src_bytes));
}
__device__ __forceinline__ void cp_commit() { asm volatile("cp.async.commit_group;"); }
template<int NN>
__device__ __forceinline__ void cp_wait() {
    asm volatile("cp.async.wait_group %0;" :: "n"(NN));
}

// Mainloop: A streamed from gmem, B streamed from gmem (both cp.async 3-stage).
__device__ __forceinline__ void mainloop_AB(
    const __half* a_src, int a_valid, const __half* b_src, int ldb,
    uint32_t as_base, uint32_t bs_base, uint32_t aw, uint32_t bw,
    int a_lane_h, int b_lane_h, int kt, float acc[4][4])
{
    const uint32_t ABUF = 64 * ASTR * 2;
    const uint32_t BBUF = BK * BSTR * 2;
    #pragma unroll
    for (int s = 0; s < STAGES - 1; s++) {
        if (s < kt) {
            int k0 = s * BK;
            cp16(aw + s * ABUF, a_src + k0, a_valid);
            cp16(bw + s * BBUF, b_src + (size_t)k0 * ldb, 16);
        }
        cp_commit();
    }
    cp_wait<STAGES - 2>();
    __syncthreads();
    for (int t = 0; t < kt; t++) {
        const int cur = t % STAGES;
        #pragma unroll
        for (int ks = 0; ks < 2; ks++) {
            const int kb = ks * 16;
            uint32_t af[4], bf[8];
            ldsm_x4(af, as_base + cur * ABUF + 2 * (a_lane_h + kb));
            ldsm_x4_t(&bf[0], bs_base + cur * BBUF + 2 * (b_lane_h + kb * BSTR));
            ldsm_x4_t(&bf[4], bs_base + cur * BBUF + 2 * (b_lane_h + kb * BSTR + 16));
            #pragma unroll
            for (int nj = 0; nj < 4; nj++)
                mma_f16(acc[nj], af, &bf[nj * 2]);
        }
        if (t + STAGES - 1 < kt) {
            int s = (t + STAGES - 1) % STAGES;
            int k0 = (t + STAGES - 1) * BK;
            cp16(aw + s * ABUF, a_src + k0, a_valid);
            cp16(bw + s * BBUF, b_src + (size_t)k0 * ldb, 16);
        }
        cp_commit();
        cp_wait<STAGES - 2>();
        __syncthreads();
    }
}

// Mainloop: A resident in smem (Hs), B streamed from gmem.
__device__ __forceinline__ void mainloop_HsB(
    uint32_t hs_lane_base, const __half* b_src, int ldb,
    uint32_t bs_base, uint32_t bw, int b_lane_h, int kt, float acc[4][4])
{
    const uint32_t BBUF = BK * BSTR * 2;
    #pragma unroll
    for (int s = 0; s < STAGES - 1; s++) {
        if (s < kt)
            cp16(bw + s * BBUF, b_src + (size_t)(s * BK) * ldb, 16);
        cp_commit();
    }
    cp_wait<STAGES - 2>();
    __syncthreads();
    for (int t = 0; t < kt; t++) {
        const int cur = t % STAGES;
        #pragma unroll
        for (int ks = 0; ks < 2; ks++) {
            const int kb = t * BK + ks * 16;
            uint32_t af[4], bf[8];
            ldsm_x4(af, hs_lane_base + 2 * kb);
            ldsm_x4_t(&bf[0], bs_base + cur * BBUF + 2 * (b_lane_h + ks * 16 * BSTR));
            ldsm_x4_t(&bf[4], bs_base + cur * BBUF + 2 * (b_lane_h + ks * 16 * BSTR + 16));
            #pragma unroll
            for (int nj = 0; nj < 4; nj++)
                mma_f16(acc[nj], af, &bf[nj * 2]);
        }
        if (t + STAGES - 1 < kt)
            cp16(bw + ((t + STAGES - 1) % STAGES) * BBUF,
                 b_src + (size_t)((t + STAGES - 1) * BK) * ldb, 16);
        cp_commit();
        cp_wait<STAGES - 2>();
        __syncthreads();
    }
}

// ---------------- fused kernel 1: h = x@W_in + b_in; [v|q|k] = h@Wqkv + bqkv -----
__global__ void __launch_bounds__(256)
fused_in_kernel(const float* __restrict__ b_in)
{
    extern __shared__ __align__(16) __half dsm[];
    __half* Hs = dsm + HS_OFF;

    const int tid  = threadIdx.x;
    const int lane = tid & 31;
    const int wid  = tid >> 5;
    const int wm   = wid & 3;
    const int wn   = wid >> 2;
    const int m0   = blockIdx.x * 64;

    const int a_row = tid >> 2, a_seg = (tid & 3) * 8;
    const int b_row = tid >> 3, b_seg = (tid & 7) * 8;

    const uint32_t as_base = (uint32_t)__cvta_generic_to_shared(dsm + AS_OFF);
    const uint32_t bs_base = (uint32_t)__cvta_generic_to_shared(dsm + BS_OFF);
    const uint32_t hs_base = (uint32_t)__cvta_generic_to_shared(Hs);
    const int a_lane_h = (wm * 16 + (lane & 15)) * ASTR + ((lane >> 4) * 8);
    const int g3 = lane >> 3;
    const int b_lane_h = ((g3 & 1) * 8 + (lane & 7)) * BSTR + (g3 >> 1) * 8 + wn * 32;
    const uint32_t aw = as_base + 2 * (a_row * ASTR + a_seg);
    const uint32_t bw = bs_base + 2 * (b_row * BSTR + b_seg);
    const uint32_t hs_lane = hs_base + 2 * ((wm * 16 + (lane & 15)) * HSTR + ((lane >> 4) * 8));

    const int a_valid = (m0 + a_row < N_NODES) ? 16 : 0;
    const __half* a_src = g_x16 + (size_t)(m0 + a_row) * DIM_IN + a_seg;

    const int lr = wm * 16 + (lane >> 2);
    const int grow = m0 + lr;

    // ---- phase A: h = x @ W_in + b_in (K=128), 4 n-chunks of 64
    for (int nc = 0; nc < 4; nc++) {
        float acc[4][4] = {};
        const __half* b_src = g_win16 + (size_t)b_row * DIM_H + nc * 64 + b_seg;
        mainloop_AB(a_src, a_valid, b_src, DIM_H,
                    as_base, bs_base, aw, bw, a_lane_h, b_lane_h, DIM_IN / BK, acc);
        #pragma unroll
        for (int nj = 0; nj < 4; nj++) {
            int c  = wn * 32 + nj * 8 + (lane & 3) * 2;
            int gc = nc * 64 + c;
            float b0 = b_in[gc], b1 = b_in[gc + 1];
            __half2 p0 = __floats2half2_rn(acc[nj][0] + b0, acc[nj][1] + b1);
            __half2 p1 = __floats2half2_rn(acc[nj][2] + b0, acc[nj][3] + b1);
            *(__half2*)&Hs[lr * HSTR + gc]       = p0;
            *(__half2*)&Hs[(lr + 8) * HSTR + gc] = p1;
            if (grow < N_NODES)     *(__half2*)&g_comb16[(size_t)grow * 512 + gc]       = p0;
            if (grow + 8 < N_NODES) *(__half2*)&g_comb16[(size_t)(grow + 8) * 512 + gc] = p1;
        }
    }
    __syncthreads();

    // ---- phase B: [v|q|k] = h(smem) @ Wqkv + bqkv (K=256), 5 n-chunks
    for (int nc = 0; nc < 5; nc++) {
        float acc[4][4] = {};
        const __half* b_src = g_wqkv16 + (size_t)b_row * NQV + nc * 64 + b_seg;
        mainloop_HsB(hs_lane, b_src, NQV, bs_base, bw, b_lane_h, DIM_H / BK, acc);
        #pragma unroll
        for (int nj = 0; nj < 4; nj++) {
            int c  = wn * 32 + nj * 8 + (lane & 3) * 2;
            int gc = nc * 64 + c;
            float b0 = g_bqkv[gc], b1 = g_bqkv[gc + 1];
            if (grow < N_NODES)
                *(__half2*)&g_qv16[(size_t)grow * NQV + gc] =
                    __floats2half2_rn(acc[nj][0] + b0, acc[nj][1] + b1);
            if (grow + 8 < N_NODES)
                *(__half2*)&g_qv16[(size_t)(grow + 8) * NQV + gc] =
                    __floats2half2_rn(acc[nj][2] + b0, acc[nj][3] + b1);
        }
    }
}

// ---------------- fused kernel 2: t = relu(comb@W1+b1); out = t@W2 + b2 ----------
__global__ void __launch_bounds__(256)
fused_mlp_kernel(const float* __restrict__ b1, const float* __restrict__ b2,
                 float* __restrict__ out)
{
    extern __shared__ __align__(16) __half dsm[];
    __half* Ts = dsm + HS_OFF;

    const int tid  = threadIdx.x;
    const int lane = tid & 31;
    const int wid  = tid >> 5;
    const int wm   = wid & 3;
    const int wn   = wid >> 2;
    const int m0   = blockIdx.x * 64;

    const int a_row = tid >> 2, a_seg = (tid & 3) * 8;
    const int b_row = tid >> 3, b_seg = (tid & 7) * 8;

    const uint32_t as_base = (uint32_t)__cvta_generic_to_shared(dsm + AS_OFF);
    const uint32_t bs_base = (uint32_t)__cvta_generic_to_shared(dsm + BS_OFF);
    const uint32_t ts_base = (uint32_t)__cvta_generic_to_shared(Ts);
    const int a_lane_h = (wm * 16 + (lane & 15)) * ASTR + ((lane >> 4) * 8);
    const int g3 = lane >> 3;
    const int b_lane_h = ((g3 & 1) * 8 + (lane & 7)) * BSTR + (g3 >> 1) * 8 + wn * 32;
    const uint32_t aw = as_base + 2 * (a_row * ASTR + a_seg);
    const uint32_t bw = bs_base + 2 * (b_row * BSTR + b_seg);
    const uint32_t ts_lane = ts_base + 2 * ((wm * 16 + (lane & 15)) * HSTR + ((lane >> 4) * 8));

    const int a_valid = (m0 + a_row < N_NODES) ? 16 : 0;
    const __half* a_src = g_comb16 + (size_t)(m0 + a_row) * 512 + a_seg;

    const int lr = wm * 16 + (lane >> 2);
    const int grow = m0 + lr;

    // ---- phase A: t = relu(comb @ W1 + b1) (K=512), 4 n-chunks, smem only
    for (int nc = 0; nc < 4; nc++) {
        float acc[4][4] = {};
        const __half* b_src = g_w116 + (size_t)b_row * DIM_H + nc * 64 + b_seg;
        mainloop_AB(a_src, a_valid, b_src, DIM_H,
                    as_base, bs_base, aw, bw, a_lane_h, b_lane_h, 512 / BK, acc);
        #pragma unroll
        for (int nj = 0; nj < 4; nj++) {
            int c  = wn * 32 + nj * 8 + (lane & 3) * 2;
            int gc = nc * 64 + c;
            float b0 = b1[gc], b1v = b1[gc + 1];
            *(__half2*)&Ts[lr * HSTR + gc] =
                __floats2half2_rn(fmaxf(acc[nj][0] + b0, 0.f), fmaxf(acc[nj][1] + b1v, 0.f));
            *(__half2*)&Ts[(lr + 8) * HSTR + gc] =
                __floats2half2_rn(fmaxf(acc[nj][2] + b0, 0.f), fmaxf(acc[nj][3] + b1v, 0.f));
        }
    }
    __syncthreads();

    // ---- phase B: out = t(smem) @ W2 + b2 (K=256, N=64), fp32 out
    {
        float acc[4][4] = {};
        const __half* b_src = g_w216 + (size_t)b_row * DIM_OUT + b_seg;
        mainloop_HsB(ts_lane, b_src, DIM_OUT, bs_base, bw, b_lane_h, DIM_H / BK, acc);
        #pragma unroll
        for (int nj = 0; nj < 4; nj++) {
            int c = wn * 32 + nj * 8 + (lane & 3) * 2;
            float b0 = b2[c], b1v = b2[c + 1];
            if (grow < N_NODES)
                *(float2*)&out[(size_t)grow * DIM_OUT + c] =
                    make_float2(acc[nj][0] + b0, acc[nj][1] + b1v);
            if (grow + 8 < N_NODES)
                *(float2*)&out[(size_t)(grow + 8) * DIM_OUT + c] =
                    make_float2(acc[nj][2] + b0, acc[nj][3] + b1v);
        }
    }
}

// ---------------- sparse softmax attention (shared-bitmap dedup) ----------------
__device__ __forceinline__ float warpSum(float v) {
    #pragma unroll
    for (int o = 16; o > 0; o >>= 1) v += __shfl_xor_sync(0xffffffffu, v, o);
    return v;
}

__global__ void __launch_bounds__(256) attn_kernel() {
    int row = blockIdx.x;
    int tid = threadIdx.x;

    __shared__ unsigned bmp[BMPW];
    __shared__ float s_w[CAP];
    __shared__ int   s_j[CAP];
    __shared__ float s_q[DIM_C];
    __shared__ float red[8];
    __shared__ float2 s_part[256];

    for (int i = tid; i < BMPW; i += 256) bmp[i] = 0u;
    if (tid < DIM_C) s_q[tid] = __half2float(g_qv16[(size_t)row * NQV + 256 + tid]);
    int cnt = g_cnt[row];
    if (cnt > CAP) cnt = CAP;
    __syncthreads();

    float e = 0.f;
    if (tid < cnt) {
        int j = g_adj[row * CAP + tid];
        s_j[tid] = j;
        unsigned bit = 1u << (j & 31);
        unsigned old = atomicOr(&bmp[j >> 5], bit);
        if (!(old & bit)) {  // first occurrence only; dups keep e=0
            const __half2* kp = (const __half2*)(g_qv16 + (size_t)j * NQV + 288);
            float s = 0.f;
            #pragma unroll
            for (int c = 0; c < DIM_C / 2; c++) {
                float2 f = __half22float2(kp[c]);
                s += s_q[2 * c] * f.x + s_q[2 * c + 1] * f.y;
            }
            e = __expf(s * 0.17677669529663687f);   // 1/sqrt(32)
        }
    }

    float s1 = warpSum(e);
    if ((tid & 31) == 0) red[tid >> 5] = s1;
    __syncthreads();
    if (tid < 32) {
        float t = (tid < 8) ? red[tid] : 0.f;
        t = warpSum(t);
        if (tid == 0) red[0] = t;
    }
    __syncthreads();
    float sum = red[0];

    if (tid < cnt) s_w[tid] = e / sum;
    __syncthreads();

    const int col = tid & 127;
    const int sel = tid >> 7;
    float2 acc = make_float2(0.f, 0.f);
    #pragma unroll 4
    for (int t = sel; t < cnt; t += 2) {
        float w = s_w[t];
        const __half2 h2 = *(const __half2*)(g_qv16 + (size_t)s_j[t] * NQV + 2 * col);
        float2 f = __half22float2(h2);
        acc.x += w * f.x;
        acc.y += w * f.y;
    }
    s_part[tid] = acc;
    __syncthreads();
    if (tid < 128) {
        float2 o = s_part[tid + 128];
        acc = s_part[tid];
        acc.x += o.x; acc.y += o.y;
        *(__half2*)&g_comb16[(size_t)row * (2 * DIM_H) + DIM_H + 2 * col] =
            __floats2half2_rn(acc.x, acc.y);
    }
}

// ---------------- launch ----------------------------------------------------------
extern "C" void kernel_launch(void* const* d_in, const int* in_sizes, int n_in,
                              void* d_out, int out_size) {
    const float* x    = (const float*)d_in[0];
    const int*   ei   = (const int*)  d_in[1];
    const float* W_in = (const float*)d_in[2];
    const float* b_in = (const float*)d_in[3];
    const float* Wq   = (const float*)d_in[4];
    const float* bq   = (const float*)d_in[5];
    const float* Wk   = (const float*)d_in[6];
    const float* bk   = (const float*)d_in[7];
    const float* Wv   = (const float*)d_in[8];
    const float* bv   = (const float*)d_in[9];
    const float* W1   = (const float*)d_in[10];
    const float* b1   = (const float*)d_in[11];
    const float* W2   = (const float*)d_in[12];
    const float* b2   = (const float*)d_in[13];
    float* out = (float*)d_out;

    static bool attr_done = false;
    if (!attr_done) {
        cudaFuncSetAttribute(fused_in_kernel,
                             cudaFuncAttributeMaxDynamicSharedMemorySize, SMEM_BYTES);
        cudaFuncSetAttribute(fused_mlp_kernel,
                             cudaFuncAttributeMaxDynamicSharedMemorySize, SMEM_BYTES);
        attr_done = true;
    }

    const int MG = (N_NODES + 63) / 64;   // 157

    prep_kernel  <<< 640, 256 >>> (x, W_in, Wq, bq, Wk, bk, Wv, bv, W1, W2);
    insert_kernel<<< (N_EDGES + 255) / 256, 256 >>> (ei);
    fused_in_kernel <<< MG, 256, SMEM_BYTES >>> (b_in);
    attn_kernel     <<< N_NODES, 256 >>> ();
    fused_mlp_kernel<<< MG, 256, SMEM_BYTES >>> (b1, b2, out);
}

// round 12
// speedup vs baseline: 1.1854x; 1.1854x over previous
#include <cuda_runtime.h>
#include <cuda_fp16.h>
#include <cstdint>

#define N_NODES 10000
#define N_EDGES 320000
#define DIM_IN  128
#define DIM_H   256
#define DIM_C   32
#define DIM_OUT 64
#define CAP     128
#define BMPW    313   // ceil(10000/32)
#define NQV     320   // v(256) | q(32) | k(32)

// ---------------- scratch (device globals) ------------------------------------
__device__ int    g_cnt[N_NODES];
__device__ int    g_adj[N_NODES * CAP];
__device__ __half g_x16  [(size_t)N_NODES * DIM_IN];
__device__ __half g_win16[DIM_IN * DIM_H];
__device__ __half g_wqkv16[DIM_H * NQV];                 // [Wv | Wq | Wk]
__device__ __half g_w116 [2 * DIM_H * DIM_H];
__device__ __half g_w216 [DIM_H * DIM_OUT];
__device__ __half g_comb16[(size_t)N_NODES * 2 * DIM_H]; // [h | comm], ld=512
__device__ __half g_qv16 [(size_t)N_NODES * NQV];        // [v | q | k], ld=320
__device__ __half g_t16  [(size_t)N_NODES * DIM_H];
__device__ float  g_bqkv[NQV];

// ---------------- prep: zero counts, convert x + weights to fp16 ----------------
__global__ void prep_kernel(const float* __restrict__ x,
                            const float* __restrict__ W_in,
                            const float* __restrict__ Wq, const float* __restrict__ bq,
                            const float* __restrict__ Wk, const float* __restrict__ bk,
                            const float* __restrict__ Wv, const float* __restrict__ bv,
                            const float* __restrict__ W1,
                            const float* __restrict__ W2) {
    int g = blockIdx.x * blockDim.x + threadIdx.x;
    int stride = gridDim.x * blockDim.x;
    for (int i = g; i < N_NODES * DIM_IN; i += stride) g_x16[i] = __float2half_rn(x[i]);
    for (int i = g; i < DIM_IN * DIM_H;  i += stride) g_win16[i] = __float2half_rn(W_in[i]);
    for (int i = g; i < 2 * DIM_H * DIM_H; i += stride) g_w116[i] = __float2half_rn(W1[i]);
    for (int i = g; i < DIM_H * DIM_OUT; i += stride) g_w216[i] = __float2half_rn(W2[i]);
    for (int i = g; i < DIM_H * NQV; i += stride) {
        int r = i / NQV, c = i % NQV;
        float w;
        if (c < 256)      w = Wv[r * 256 + c];
        else if (c < 288) w = Wq[r * 32 + (c - 256)];
        else              w = Wk[r * 32 + (c - 288)];
        g_wqkv16[i] = __float2half_rn(w);
    }
    for (int i = g; i < NQV; i += stride)
        g_bqkv[i] = (i < 256) ? bv[i] : (i < 288 ? bq[i - 256] : bk[i - 288]);
    for (int i = g; i < N_NODES; i += stride) g_cnt[i] = 0;
}

// ---------------- adjacency: append (dups deduped later in attn) ----------------
__global__ void insert_kernel(const int* __restrict__ ei) {
    int e = blockIdx.x * blockDim.x + threadIdx.x;
    if (e >= N_EDGES) return;
    int i = ei[e];
    int j = ei[N_EDGES + e];
    int pos = atomicAdd(&g_cnt[i], 1);
    if (pos < CAP) g_adj[i * CAP + pos] = j;
}

// ---------------- FP16 tensor-core GEMM, 8 warps, cp.async.ca 3-stage -----------
// C[M,N] = A[M,K] @ B[K,N] + bias (opt relu). TBM x 64 x 32 tiles.
// 256 threads = 8 warps (4 along M x 2 along N); warp tile (TBM/4) x 32.
#define BN 64
#define BK 32
#define ASTR 40   // As row stride (halves): ldmatrix phases hit all 32 banks
#define BSTR 72   // Bs row stride (halves): same
#define STAGES 3

__device__ __forceinline__ void ldsm_x4(uint32_t* r, uint32_t addr) {
    asm volatile("ldmatrix.sync.aligned.m8n8.x4.shared.b16 {%0,%1,%2,%3}, [%4];"
        : "=r"(r[0]), "=r"(r[1]), "=r"(r[2]), "=r"(r[3]) : "r"(addr));
}
__device__ __forceinline__ void ldsm_x4_t(uint32_t* r, uint32_t addr) {
    asm volatile("ldmatrix.sync.aligned.m8n8.x4.trans.shared.b16 {%0,%1,%2,%3}, [%4];"
        : "=r"(r[0]), "=r"(r[1]), "=r"(r[2]), "=r"(r[3]) : "r"(addr));
}
__device__ __forceinline__ void mma_f16(float* d, const uint32_t* a, const uint32_t* b) {
    asm volatile("mma.sync.aligned.m16n8k16.row.col.f32.f16.f16.f32 "
        "{%0,%1,%2,%3}, {%4,%5,%6,%7}, {%8,%9}, {%0,%1,%2,%3};"
        : "+f"(d[0]), "+f"(d[1]), "+f"(d[2]), "+f"(d[3])
        : "r"(a[0]), "r"(a[1]), "r"(a[2]), "r"(a[3]), "r"(b[0]), "r"(b[1]));
}
// .ca keeps L1 allocation (R7 regression was caused by .cg's L1 bypass)
__device__ __forceinline__ void cp16(uint32_t dst, const void* src, int src_bytes) {
    asm volatile("cp.async.ca.shared.global [%0], [%1], 16, %2;"
        :: "r"(dst), "l"(src), "r"(src_bytes));
}
__device__ __forceinline__ void cp_commit() { asm volatile("cp.async.commit_group;"); }
template<int NN>
__device__ __forceinline__ void cp_wait() {
    asm volatile("cp.async.wait_group %0;" :: "n"(NN));
}

template<int TBM, int OUT16>
__global__ void __launch_bounds__(256, 3)
gemm_f16(const __half* __restrict__ A, int lda,
         const __half* __restrict__ B, int ldb,
         const float* __restrict__ bias,
         void* __restrict__ Cv, int ldc,
         int M, int K, int relu)
{
    constexpr int MI = TBM / 64;             // m16 frags per warp (1 or 2)
    __shared__ __align__(16) __half As[STAGES][TBM * ASTR];
    __shared__ __align__(16) __half Bs[STAGES][BK * BSTR];

    const int tid  = threadIdx.x;
    const int lane = tid & 31;
    const int wid  = tid >> 5;
    const int wm   = wid & 3;        // 4 warps along M
    const int wn   = wid >> 2;       // 2 warps along N (32 cols each)
    const int m0   = blockIdx.y * TBM;
    const int n0   = blockIdx.x * BN;

    const int a_row = tid >> 2;              // 0..63 (pass p adds +64*p)
    const int a_seg = (tid & 3) * 8;         // halves
    const int b_row = tid >> 3;              // 0..31
    const int b_seg = (tid & 7) * 8;

    const uint32_t as_base = (uint32_t)__cvta_generic_to_shared(&As[0][0]);
    const uint32_t bs_base = (uint32_t)__cvta_generic_to_shared(&Bs[0][0]);
    const int a_lane_h = (wm * (16 * MI) + (lane & 15)) * ASTR + ((lane >> 4) * 8);
    const int g3 = lane >> 3;
    const int b_lane_h = ((g3 & 1) * 8 + (lane & 7)) * BSTR + (g3 >> 1) * 8 + wn * 32;
    const uint32_t ABUF = TBM * ASTR * 2;    // bytes per A stage
    const uint32_t BBUF = BK * BSTR * 2;

    const uint32_t aw = as_base + 2 * (a_row * ASTR + a_seg);
    const uint32_t bw = bs_base + 2 * (b_row * BSTR + b_seg);
    int a_valid[MI];
    const __half* a_src[MI];
    #pragma unroll
    for (int p = 0; p < MI; p++) {
        a_valid[p] = (m0 + p * 64 + a_row < M) ? 16 : 0;
        a_src[p] = A + (size_t)(m0 + p * 64 + a_row) * lda + a_seg;
    }
    const __half* b_src = B + (size_t)b_row * ldb + n0 + b_seg;

    float acc[MI][4][4];
    #pragma unroll
    for (int i = 0; i < MI; i++)
        #pragma unroll
        for (int j = 0; j < 4; j++)
            #pragma unroll
            for (int r = 0; r < 4; r++) acc[i][j][r] = 0.f;

    const int kt = K / BK;

    #pragma unroll
    for (int s = 0; s < STAGES - 1; s++) {
        if (s < kt) {
            int k0 = s * BK;
            #pragma unroll
            for (int p = 0; p < MI; p++)
                cp16(aw + s * ABUF + p * 64 * ASTR * 2, a_src[p] + k0, a_valid[p]);
            cp16(bw + s * BBUF, b_src + (size_t)k0 * ldb, 16);
        }
        cp_commit();
    }
    cp_wait<STAGES - 2>();
    __syncthreads();

    for (int t = 0; t < kt; t++) {
        const int cur = t % STAGES;
        #pragma unroll
        for (int ks = 0; ks < 2; ks++) {
            const int kb = ks * 16;
            uint32_t af[MI][4], bf[8];
            #pragma unroll
            for (int mi = 0; mi < MI; mi++)
                ldsm_x4(af[mi], as_base + cur * ABUF + 2 * (a_lane_h + mi * 16 * ASTR + kb));
            #pragma unroll
            for (int nh = 0; nh < 2; nh++)
                ldsm_x4_t(&bf[nh * 4], bs_base + cur * BBUF + 2 * (b_lane_h + kb * BSTR + nh * 16));
            #pragma unroll
            for (int mi = 0; mi < MI; mi++)
                #pragma unroll
                for (int nj = 0; nj < 4; nj++)
                    mma_f16(acc[mi][nj], af[mi], &bf[nj * 2]);
        }

        if (t + STAGES - 1 < kt) {
            int s = (t + STAGES - 1) % STAGES;
            int k0 = (t + STAGES - 1) * BK;
            #pragma unroll
            for (int p = 0; p < MI; p++)
                cp16(aw + s * ABUF + p * 64 * ASTR * 2, a_src[p] + k0, a_valid[p]);
            cp16(bw + s * BBUF, b_src + (size_t)k0 * ldb, 16);
        }
        cp_commit();
        cp_wait<STAGES - 2>();
        __syncthreads();
    }

    #pragma unroll
    for (int mi = 0; mi < MI; mi++) {
        int r0 = m0 + wm * (16 * MI) + mi * 16 + (lane >> 2);
        #pragma unroll
        for (int nj = 0; nj < 4; nj++) {
            int col = n0 + wn * 32 + nj * 8 + (lane & 3) * 2;
            float b0 = bias[col], b1 = bias[col + 1];
            float v0 = acc[mi][nj][0] + b0, v1 = acc[mi][nj][1] + b1;
            float v2 = acc[mi][nj][2] + b0, v3 = acc[mi][nj][3] + b1;
            if (relu) {
                v0 = fmaxf(v0, 0.f); v1 = fmaxf(v1, 0.f);
                v2 = fmaxf(v2, 0.f); v3 = fmaxf(v3, 0.f);
            }
            if (OUT16) {
                __half* C = (__half*)Cv;
                if (r0 < M)     *(__half2*)&C[(size_t)r0 * ldc + col]       = __floats2half2_rn(v0, v1);
                if (r0 + 8 < M) *(__half2*)&C[(size_t)(r0 + 8) * ldc + col] = __floats2half2_rn(v2, v3);
            } else {
                float* C = (float*)Cv;
                if (r0 < M)     *(float2*)&C[(size_t)r0 * ldc + col]       = make_float2(v0, v1);
                if (r0 + 8 < M) *(float2*)&C[(size_t)(r0 + 8) * ldc + col] = make_float2(v2, v3);
            }
        }
    }
}

// ---------------- sparse softmax attention (shared-bitmap dedup) ----------------
// Scores are tiny (|sc| << 1): exp() is range-safe, no max-subtraction pass.
// v-gather: 4 neighbors in parallel (one per 64-thread group), half4 (LDG.64) loads.
__device__ __forceinline__ float warpSum(float v) {
    #pragma unroll
    for (int o = 16; o > 0; o >>= 1) v += __shfl_xor_sync(0xffffffffu, v, o);
    return v;
}

__global__ void __launch_bounds__(256) attn_kernel() {
    int row = blockIdx.x;
    int tid = threadIdx.x;

    __shared__ unsigned bmp[BMPW];
    __shared__ float s_w[CAP];
    __shared__ int   s_j[CAP];
    __shared__ float s_q[DIM_C];
    __shared__ float red[8];
    __shared__ float4 s_part[256];

    for (int i = tid; i < BMPW; i += 256) bmp[i] = 0u;
    if (tid < DIM_C) s_q[tid] = __half2float(g_qv16[(size_t)row * NQV + 256 + tid]);
    int cnt = g_cnt[row];
    if (cnt > CAP) cnt = CAP;
    __syncthreads();

    float e = 0.f;
    if (tid < cnt) {
        int j = g_adj[row * CAP + tid];
        s_j[tid] = j;
        unsigned bit = 1u << (j & 31);
        unsigned old = atomicOr(&bmp[j >> 5], bit);
        if (!(old & bit)) {  // first occurrence only; dups keep e=0
            const __half2* kp = (const __half2*)(g_qv16 + (size_t)j * NQV + 288);
            float s = 0.f;
            #pragma unroll
            for (int c = 0; c < DIM_C / 2; c++) {
                float2 f = __half22float2(kp[c]);
                s += s_q[2 * c] * f.x + s_q[2 * c + 1] * f.y;
            }
            e = __expf(s * 0.17677669529663687f);   // 1/sqrt(32)
        }
    }

    float s1 = warpSum(e);
    if ((tid & 31) == 0) red[tid >> 5] = s1;
    __syncthreads();
    if (tid < 32) {
        float t = (tid < 8) ? red[tid] : 0.f;
        t = warpSum(t);
        if (tid == 0) red[0] = t;
    }
    __syncthreads();
    float sum = red[0];

    if (tid < cnt) s_w[tid] = e / sum;
    __syncthreads();

    // gather: group g handles neighbors t = g, g+4, ...; thread loads half4.
    const int grp = tid >> 6;        // 0..3
    const int c4  = tid & 63;        // half4 chunk -> columns 4*c4 .. 4*c4+3
    float4 acc = make_float4(0.f, 0.f, 0.f, 0.f);
    for (int t = grp; t < cnt; t += 4) {
        float w = s_w[t];
        const uint2 d = *(const uint2*)(g_qv16 + (size_t)s_j[t] * NQV + 4 * c4);
        float2 f0 = __half22float2(*(const __half2*)&d.x);
        float2 f1 = __half22float2(*(const __half2*)&d.y);
        acc.x += w * f0.x; acc.y += w * f0.y;
        acc.z += w * f1.x; acc.w += w * f1.y;
    }
    s_part[tid] = acc;
    __syncthreads();
    if (tid < 64) {
        float4 a = s_part[tid];
        float4 b = s_part[tid + 64];
        float4 c = s_part[tid + 128];
        float4 d = s_part[tid + 192];
        a.x += b.x + c.x + d.x;
        a.y += b.y + c.y + d.y;
        a.z += b.z + c.z + d.z;
        a.w += b.w + c.w + d.w;
        __half2 lo = __floats2half2_rn(a.x, a.y);
        __half2 hi = __floats2half2_rn(a.z, a.w);
        uint2 pk;
        pk.x = *(uint32_t*)&lo;
        pk.y = *(uint32_t*)&hi;
        *(uint2*)&g_comb16[(size_t)row * (2 * DIM_H) + DIM_H + 4 * tid] = pk;
    }
}

// ---------------- launch ----------------------------------------------------------
extern "C" void kernel_launch(void* const* d_in, const int* in_sizes, int n_in,
                              void* d_out, int out_size) {
    const float* x    = (const float*)d_in[0];
    const int*   ei   = (const int*)  d_in[1];
    const float* W_in = (const float*)d_in[2];
    const float* b_in = (const float*)d_in[3];
    const float* Wq   = (const float*)d_in[4];
    const float* bq   = (const float*)d_in[5];
    const float* Wk   = (const float*)d_in[6];
    const float* bk   = (const float*)d_in[7];
    const float* Wv   = (const float*)d_in[8];
    const float* bv   = (const float*)d_in[9];
    const float* W1   = (const float*)d_in[10];
    const float* b1   = (const float*)d_in[11];
    const float* W2   = (const float*)d_in[12];
    const float* b2   = (const float*)d_in[13];
    float* out = (float*)d_out;

    __half *x16, *win16, *wqkv16, *w116, *w216, *comb16, *qv16, *t16;
    float *bqkv;
    cudaGetSymbolAddress((void**)&x16,    g_x16);
    cudaGetSymbolAddress((void**)&win16,  g_win16);
    cudaGetSymbolAddress((void**)&wqkv16, g_wqkv16);
    cudaGetSymbolAddress((void**)&w116,   g_w116);
    cudaGetSymbolAddress((void**)&w216,   g_w216);
    cudaGetSymbolAddress((void**)&comb16, g_comb16);
    cudaGetSymbolAddress((void**)&qv16,   g_qv16);
    cudaGetSymbolAddress((void**)&t16,    g_t16);
    cudaGetSymbolAddress((void**)&bqkv,   g_bqkv);

    const int MG128 = (N_NODES + 127) / 128;   // 79
    const int MG64  = (N_NODES + 63) / 64;     // 157

    prep_kernel  <<< 640, 256 >>> (x, W_in, Wq, bq, Wk, bk, Wv, bv, W1, W2);
    insert_kernel<<< (N_EDGES + 255) / 256, 256 >>> (ei);

    // h = x @ W_in + b_in  -> comb16[:, :256]
    gemm_f16<128,1><<< dim3(4, MG128), 256 >>>(x16, DIM_IN, win16, DIM_H, b_in,
                                               comb16, 2 * DIM_H, N_NODES, DIM_IN, 0);
    // [v|q|k] = h @ [Wv|Wq|Wk] + [bv|bq|bk]   (N=320)
    gemm_f16<128,1><<< dim3(5, MG128), 256 >>>(comb16, 2 * DIM_H, wqkv16, NQV, bqkv,
                                               qv16, NQV, N_NODES, DIM_H, 0);
    // sparse softmax attention -> comb16[:, 256:]
    attn_kernel<<< N_NODES, 256 >>>();
    // t = relu(combined @ W1 + b1)
    gemm_f16<128,1><<< dim3(4, MG128), 256 >>>(comb16, 2 * DIM_H, w116, DIM_H, b1,
                                               t16, DIM_H, N_NODES, 2 * DIM_H, 1);
    // out = t @ W2 + b2  (fp32 out)
    gemm_f16<64,0><<< dim3(1, MG64), 256 >>>(t16, DIM_H, w216, DIM_OUT, b2,
                                             out, DIM_OUT, N_NODES, DIM_H, 0);
}

// round 16
// speedup vs baseline: 1.2484x; 1.0531x over previous
#include <cuda_runtime.h>
#include <cuda_fp16.h>
#include <cstdint>

#define N_NODES 10000
#define N_EDGES 320000
#define DIM_IN  128
#define DIM_H   256
#define DIM_C   32
#define DIM_OUT 64
#define CAP     128
#define BMPW    313   // ceil(10000/32)
#define NQV     320   // v(256) | q(32) | k(32)

// ---------------- scratch (device globals; 16B-aligned for vector access) ------
__device__ int    g_cnt[N_NODES];
__device__ int    g_adj[N_NODES * CAP];
__device__ __align__(16) __half g_x16  [(size_t)N_NODES * DIM_IN];
__device__ __align__(16) __half g_win16[DIM_IN * DIM_H];
__device__ __align__(16) __half g_wqkv16[DIM_H * NQV];           // [Wv | Wq | Wk]
__device__ __align__(16) __half g_w116 [2 * DIM_H * DIM_H];
__device__ __align__(16) __half g_w216 [DIM_H * DIM_OUT];
__device__ __align__(16) __half g_comb16[(size_t)N_NODES * 2 * DIM_H]; // [h|comm]
__device__ __align__(16) __half g_qv16 [(size_t)N_NODES * NQV];  // [v|q|k], ld=320
__device__ __align__(16) __half g_t16  [(size_t)N_NODES * DIM_H];
__device__ float  g_bqkv[NQV];

// ---------------- prep: zero counts, convert x + weights to fp16 ----------------
__global__ void prep_kernel(const float* __restrict__ x,
                            const float* __restrict__ W_in,
                            const float* __restrict__ Wq, const float* __restrict__ bq,
                            const float* __restrict__ Wk, const float* __restrict__ bk,
                            const float* __restrict__ Wv, const float* __restrict__ bv,
                            const float* __restrict__ W1,
                            const float* __restrict__ W2) {
    int g = blockIdx.x * blockDim.x + threadIdx.x;
    int stride = gridDim.x * blockDim.x;
    for (int i = g; i < N_NODES * DIM_IN; i += stride) g_x16[i] = __float2half_rn(x[i]);
    for (int i = g; i < DIM_IN * DIM_H;  i += stride) g_win16[i] = __float2half_rn(W_in[i]);
    for (int i = g; i < 2 * DIM_H * DIM_H; i += stride) g_w116[i] = __float2half_rn(W1[i]);
    for (int i = g; i < DIM_H * DIM_OUT; i += stride) g_w216[i] = __float2half_rn(W2[i]);
    for (int i = g; i < DIM_H * NQV; i += stride) {
        int r = i / NQV, c = i % NQV;
        float w;
        if (c < 256)      w = Wv[r * 256 + c];
        else if (c < 288) w = Wq[r * 32 + (c - 256)];
        else              w = Wk[r * 32 + (c - 288)];
        g_wqkv16[i] = __float2half_rn(w);
    }
    for (int i = g; i < NQV; i += stride)
        g_bqkv[i] = (i < 256) ? bv[i] : (i < 288 ? bq[i - 256] : bk[i - 288]);
    for (int i = g; i < N_NODES; i += stride) g_cnt[i] = 0;
}

// ---------------- adjacency: append (dups deduped later in attn) ----------------
__global__ void insert_kernel(const int* __restrict__ ei) {
    int e = blockIdx.x * blockDim.x + threadIdx.x;
    if (e >= N_EDGES) return;
    int i = ei[e];
    int j = ei[N_EDGES + e];
    int pos = atomicAdd(&g_cnt[i], 1);
    if (pos < CAP) g_adj[i * CAP + pos] = j;
}

// ---------------- FP16 tensor-core GEMM, 8 warps, cp.async.ca 3-stage -----------
// C[M,N] = A[M,K] @ B[K,N] + bias (opt relu). TBM x 64 x 32 tiles.
// 256 threads = 8 warps (4 along M x 2 along N); warp tile (TBM/4) x 32.
#define BN 64
#define BK 32
#define ASTR 40   // As row stride (halves): ldmatrix phases hit all 32 banks
#define BSTR 72   // Bs row stride (halves): same
#define STAGES 3

__device__ __forceinline__ void ldsm_x4(uint32_t* r, uint32_t addr) {
    asm volatile("ldmatrix.sync.aligned.m8n8.x4.shared.b16 {%0,%1,%2,%3}, [%4];"
        : "=r"(r[0]), "=r"(r[1]), "=r"(r[2]), "=r"(r[3]) : "r"(addr));
}
__device__ __forceinline__ void ldsm_x4_t(uint32_t* r, uint32_t addr) {
    asm volatile("ldmatrix.sync.aligned.m8n8.x4.trans.shared.b16 {%0,%1,%2,%3}, [%4];"
        : "=r"(r[0]), "=r"(r[1]), "=r"(r[2]), "=r"(r[3]) : "r"(addr));
}
__device__ __forceinline__ void mma_f16(float* d, const uint32_t* a, const uint32_t* b) {
    asm volatile("mma.sync.aligned.m16n8k16.row.col.f32.f16.f16.f32 "
        "{%0,%1,%2,%3}, {%4,%5,%6,%7}, {%8,%9}, {%0,%1,%2,%3};"
        : "+f"(d[0]), "+f"(d[1]), "+f"(d[2]), "+f"(d[3])
        : "r"(a[0]), "r"(a[1]), "r"(a[2]), "r"(a[3]), "r"(b[0]), "r"(b[1]));
}
// .ca keeps L1 allocation (R7 regression was caused by .cg's L1 bypass)
__device__ __forceinline__ void cp16(uint32_t dst, const void* src, int src_bytes) {
    asm volatile("cp.async.ca.shared.global [%0], [%1], 16, %2;"
        :: "r"(dst), "l"(src), "r"(src_bytes));
}
__device__ __forceinline__ void cp_commit() { asm volatile("cp.async.commit_group;"); }
template<int NN>
__device__ __forceinline__ void cp_wait() {
    asm volatile("cp.async.wait_group %0;" :: "n"(NN));
}

template<int TBM, int OUT16>
__global__ void __launch_bounds__(256, 3)
gemm_f16(const __half* __restrict__ A, int lda,
         const __half* __restrict__ B, int ldb,
         const float* __restrict__ bias,
         void* __restrict__ Cv, int ldc,
         int M, int K, int relu)
{
    constexpr int MI = TBM / 64;             // m16 frags per warp (1 or 2)
    __shared__ __align__(16) __half As[STAGES][TBM * ASTR];
    __shared__ __align__(16) __half Bs[STAGES][BK * BSTR];

    const int tid  = threadIdx.x;
    const int lane = tid & 31;
    const int wid  = tid >> 5;
    const int wm   = wid & 3;        // 4 warps along M
    const int wn   = wid >> 2;       // 2 warps along N (32 cols each)
    const int m0   = blockIdx.y * TBM;
    const int n0   = blockIdx.x * BN;

    const int a_row = tid >> 2;              // 0..63 (pass p adds +64*p)
    const int a_seg = (tid & 3) * 8;         // halves
    const int b_row = tid >> 3;              // 0..31
    const int b_seg = (tid & 7) * 8;

    const uint32_t as_base = (uint32_t)__cvta_generic_to_shared(&As[0][0]);
    const uint32_t bs_base = (uint32_t)__cvta_generic_to_shared(&Bs[0][0]);
    const int a_lane_h = (wm * (16 * MI) + (lane & 15)) * ASTR + ((lane >> 4) * 8);
    const int g3 = lane >> 3;
    const int b_lane_h = ((g3 & 1) * 8 + (lane & 7)) * BSTR + (g3 >> 1) * 8 + wn * 32;
    const uint32_t ABUF = TBM * ASTR * 2;    // bytes per A stage
    const uint32_t BBUF = BK * BSTR * 2;

    const uint32_t aw = as_base + 2 * (a_row * ASTR + a_seg);
    const uint32_t bw = bs_base + 2 * (b_row * BSTR + b_seg);
    int a_valid[MI];
    const __half* a_src[MI];
    #pragma unroll
    for (int p = 0; p < MI; p++) {
        a_valid[p] = (m0 + p * 64 + a_row < M) ? 16 : 0;
        a_src[p] = A + (size_t)(m0 + p * 64 + a_row) * lda + a_seg;
    }
    const __half* b_src = B + (size_t)b_row * ldb + n0 + b_seg;

    float acc[MI][4][4];
    #pragma unroll
    for (int i = 0; i < MI; i++)
        #pragma unroll
        for (int j = 0; j < 4; j++)
            #pragma unroll
            for (int r = 0; r < 4; r++) acc[i][j][r] = 0.f;

    const int kt = K / BK;

    #pragma unroll
    for (int s = 0; s < STAGES - 1; s++) {
        if (s < kt) {
            int k0 = s * BK;
            #pragma unroll
            for (int p = 0; p < MI; p++)
                cp16(aw + s * ABUF + p * 64 * ASTR * 2, a_src[p] + k0, a_valid[p]);
            cp16(bw + s * BBUF, b_src + (size_t)k0 * ldb, 16);
        }
        cp_commit();
    }
    cp_wait<STAGES - 2>();
    __syncthreads();

    for (int t = 0; t < kt; t++) {
        const int cur = t % STAGES;
        #pragma unroll
        for (int ks = 0; ks < 2; ks++) {
            const int kb = ks * 16;
            uint32_t af[MI][4], bf[8];
            #pragma unroll
            for (int mi = 0; mi < MI; mi++)
                ldsm_x4(af[mi], as_base + cur * ABUF + 2 * (a_lane_h + mi * 16 * ASTR + kb));
            #pragma unroll
            for (int nh = 0; nh < 2; nh++)
                ldsm_x4_t(&bf[nh * 4], bs_base + cur * BBUF + 2 * (b_lane_h + kb * BSTR + nh * 16));
            #pragma unroll
            for (int mi = 0; mi < MI; mi++)
                #pragma unroll
                for (int nj = 0; nj < 4; nj++)
                    mma_f16(acc[mi][nj], af[mi], &bf[nj * 2]);
        }

        if (t + STAGES - 1 < kt) {
            int s = (t + STAGES - 1) % STAGES;
            int k0 = (t + STAGES - 1) * BK;
            #pragma unroll
            for (int p = 0; p < MI; p++)
                cp16(aw + s * ABUF + p * 64 * ASTR * 2, a_src[p] + k0, a_valid[p]);
            cp16(bw + s * BBUF, b_src + (size_t)k0 * ldb, 16);
        }
        cp_commit();
        cp_wait<STAGES - 2>();
        __syncthreads();
    }

    #pragma unroll
    for (int mi = 0; mi < MI; mi++) {
        int r0 = m0 + wm * (16 * MI) + mi * 16 + (lane >> 2);
        #pragma unroll
        for (int nj = 0; nj < 4; nj++) {
            int col = n0 + wn * 32 + nj * 8 + (lane & 3) * 2;
            float b0 = bias[col], b1 = bias[col + 1];
            float v0 = acc[mi][nj][0] + b0, v1 = acc[mi][nj][1] + b1;
            float v2 = acc[mi][nj][2] + b0, v3 = acc[mi][nj][3] + b1;
            if (relu) {
                v0 = fmaxf(v0, 0.f); v1 = fmaxf(v1, 0.f);
                v2 = fmaxf(v2, 0.f); v3 = fmaxf(v3, 0.f);
            }
            if (OUT16) {
                __half* C = (__half*)Cv;
                if (r0 < M)     *(__half2*)&C[(size_t)r0 * ldc + col]       = __floats2half2_rn(v0, v1);
                if (r0 + 8 < M) *(__half2*)&C[(size_t)(r0 + 8) * ldc + col] = __floats2half2_rn(v2, v3);
            } else {
                float* C = (float*)Cv;
                if (r0 < M)     *(float2*)&C[(size_t)r0 * ldc + col]       = make_float2(v0, v1);
                if (r0 + 8 < M) *(float2*)&C[(size_t)(r0 + 8) * ldc + col] = make_float2(v2, v3);
            }
        }
    }
}

// ---------------- sparse softmax attention --------------------------------------
// Coalesced: 16-lane half-warp per neighbor for scores (64B contiguous k-row),
// full warp per neighbor for the v-gather (512B contiguous row, LDG.128).
// Scores are tiny (|sc| << 1): exp() is range-safe, no max-subtraction pass.
__device__ __forceinline__ float warpSum(float v) {
    #pragma unroll
    for (int o = 16; o > 0; o >>= 1) v += __shfl_xor_sync(0xffffffffu, v, o);
    return v;
}

__global__ void __launch_bounds__(256) attn_kernel() {
    int row = blockIdx.x;
    int tid = threadIdx.x;
    const int lane = tid & 31;
    const int wid  = tid >> 5;

    __shared__ unsigned bmp[BMPW];
    __shared__ float s_w[CAP];
    __shared__ int   s_j[CAP];
    __shared__ unsigned char s_ok[CAP];
    __shared__ float s_q[DIM_C];
    __shared__ float red[8];
    __shared__ __align__(16) float s_acc[8 * 256];   // 8 warps x 256 cols

    for (int i = tid; i < BMPW; i += 256) bmp[i] = 0u;
    if (tid < DIM_C) s_q[tid] = __half2float(g_qv16[(size_t)row * NQV + 256 + tid]);
    int cnt = g_cnt[row];
    if (cnt > CAP) cnt = CAP;
    __syncthreads();

    // phase 1: load adjacency, dedup via bitmap
    if (tid < cnt) {
        int j = g_adj[row * CAP + tid];
        s_j[tid] = j;
        unsigned bit = 1u << (j & 31);
        unsigned old = atomicOr(&bmp[j >> 5], bit);
        s_ok[tid] = !(old & bit);
    }
    __syncthreads();

    // phase 2: scores, one 16-lane half-warp per neighbor (coalesced 64B row).
    // Loop bound is warp-uniform (padded to 16); shuffles always full-warp.
    {
        const int hw  = tid >> 4;    // 0..15
        const int l16 = tid & 15;
        const float q0 = s_q[2 * l16], q1 = s_q[2 * l16 + 1];
        const int cnt_pad = (cnt + 15) & ~15;
        for (int nb = hw; nb < cnt_pad; nb += 16) {
            const bool valid = (nb < cnt);
            float d = 0.f;
            if (valid) {
                int j = s_j[nb];
                float2 f = __half22float2(
                    *(const __half2*)(g_qv16 + (size_t)j * NQV + 288 + 2 * l16));
                d = q0 * f.x + q1 * f.y;
            }
            #pragma unroll
            for (int o = 8; o > 0; o >>= 1)
                d += __shfl_xor_sync(0xffffffffu, d, o, 16);
            if (valid && l16 == 0)
                s_w[nb] = s_ok[nb] ? __expf(d * 0.17677669529663687f) : 0.f;
        }
    }
    __syncthreads();

    // softmax denominator
    float e = (tid < cnt) ? s_w[tid] : 0.f;
    float s1 = warpSum(e);
    if (lane == 0) red[wid] = s1;
    __syncthreads();
    if (tid < 32) {
        float t = (tid < 8) ? red[tid] : 0.f;
        t = warpSum(t);
        if (tid == 0) red[0] = t;
    }
    __syncthreads();
    float sum = red[0];
    if (tid < cnt) s_w[tid] = e / sum;
    __syncthreads();

    // phase 3: v-gather, one warp per neighbor, LDG.128 (512B contiguous row)
    float acc[8] = {};
    for (int t = wid; t < cnt; t += 8) {
        float w = s_w[t];
        uint4 d = *(const uint4*)(g_qv16 + (size_t)s_j[t] * NQV + 8 * lane);
        const uint32_t* dw = (const uint32_t*)&d;
        #pragma unroll
        for (int p = 0; p < 4; p++) {
            float2 f = __half22float2(*(const __half2*)&dw[p]);
            acc[2 * p]     += w * f.x;
            acc[2 * p + 1] += w * f.y;
        }
    }
    #pragma unroll
    for (int i = 0; i < 4; i++)
        *(float2*)&s_acc[wid * 256 + lane * 8 + 2 * i] = make_float2(acc[2 * i], acc[2 * i + 1]);
    __syncthreads();

    // combine 8 warps' partials, write comm (fp16)
    if (tid < 128) {
        int c0 = tid * 2;
        float a0 = 0.f, a1 = 0.f;
        #pragma unroll
        for (int w = 0; w < 8; w++) {
            a0 += s_acc[w * 256 + c0];
            a1 += s_acc[w * 256 + c0 + 1];
        }
        *(__half2*)&g_comb16[(size_t)row * (2 * DIM_H) + DIM_H + c0] =
            __floats2half2_rn(a0, a1);
    }
}

// ---------------- launch ----------------------------------------------------------
extern "C" void kernel_launch(void* const* d_in, const int* in_sizes, int n_in,
                              void* d_out, int out_size) {
    const float* x    = (const float*)d_in[0];
    const int*   ei   = (const int*)  d_in[1];
    const float* W_in = (const float*)d_in[2];
    const float* b_in = (const float*)d_in[3];
    const float* Wq   = (const float*)d_in[4];
    const float* bq   = (const float*)d_in[5];
    const float* Wk   = (const float*)d_in[6];
    const float* bk   = (const float*)d_in[7];
    const float* Wv   = (const float*)d_in[8];
    const float* bv   = (const float*)d_in[9];
    const float* W1   = (const float*)d_in[10];
    const float* b1   = (const float*)d_in[11];
    const float* W2   = (const float*)d_in[12];
    const float* b2   = (const float*)d_in[13];
    float* out = (float*)d_out;

    __half *x16, *win16, *wqkv16, *w116, *w216, *comb16, *qv16, *t16;
    float *bqkv;
    cudaGetSymbolAddress((void**)&x16,    g_x16);
    cudaGetSymbolAddress((void**)&win16,  g_win16);
    cudaGetSymbolAddress((void**)&wqkv16, g_wqkv16);
    cudaGetSymbolAddress((void**)&w116,   g_w116);
    cudaGetSymbolAddress((void**)&w216,   g_w216);
    cudaGetSymbolAddress((void**)&comb16, g_comb16);
    cudaGetSymbolAddress((void**)&qv16,   g_qv16);
    cudaGetSymbolAddress((void**)&t16,    g_t16);
    cudaGetSymbolAddress((void**)&bqkv,   g_bqkv);

    const int MG128 = (N_NODES + 127) / 128;   // 79
    const int MG64  = (N_NODES + 63) / 64;     // 157

    prep_kernel  <<< 640, 256 >>> (x, W_in, Wq, bq, Wk, bk, Wv, bv, W1, W2);
    insert_kernel<<< (N_EDGES + 255) / 256, 256 >>> (ei);

    // h = x @ W_in + b_in  -> comb16[:, :256]
    gemm_f16<128,1><<< dim3(4, MG128), 256 >>>(x16, DIM_IN, win16, DIM_H, b_in,
                                               comb16, 2 * DIM_H, N_NODES, DIM_IN, 0);
    // [v|q|k] = h @ [Wv|Wq|Wk] + [bv|bq|bk]   (N=320)
    gemm_f16<128,1><<< dim3(5, MG128), 256 >>>(comb16, 2 * DIM_H, wqkv16, NQV, bqkv,
                                               qv16, NQV, N_NODES, DIM_H, 0);
    // sparse softmax attention -> comb16[:, 256:]
    attn_kernel<<< N_NODES, 256 >>>();
    // t = relu(combined @ W1 + b1)
    gemm_f16<128,1><<< dim3(4, MG128), 256 >>>(comb16, 2 * DIM_H, w116, DIM_H, b1,
                                               t16, DIM_H, N_NODES, 2 * DIM_H, 1);
    // out = t @ W2 + b2  (fp32 out)
    gemm_f16<64,0><<< dim3(1, MG64), 256 >>>(t16, DIM_H, w216, DIM_OUT, b2,
                                             out, DIM_OUT, N_NODES, DIM_H, 0);
}

// round 17
// speedup vs baseline: 1.3315x; 1.0666x over previous
#include <cuda_runtime.h>
#include <cuda_fp16.h>
#include <cstdint>

#define N_NODES 10000
#define N_EDGES 320000
#define DIM_IN  128
#define DIM_H   256
#define DIM_C   32
#define DIM_OUT 64
#define CAP     128
#define BMPW    313   // ceil(10000/32)
#define NQV     320   // v(256) | q(32) | k(32)

// ---------------- scratch (device globals; 16B-aligned for vector access) ------
__device__ int    g_cnt[N_NODES];
__device__ int    g_adj[N_NODES * CAP];
__device__ __align__(16) __half g_x16  [(size_t)N_NODES * DIM_IN];
__device__ __align__(16) __half g_win16[DIM_IN * DIM_H];
__device__ __align__(16) __half g_wqkv16[DIM_H * NQV];           // [Wv | Wq | Wk]
__device__ __align__(16) __half g_w116 [2 * DIM_H * DIM_H];
__device__ __align__(16) __half g_w216 [DIM_H * DIM_OUT];
__device__ __align__(16) __half g_comb16[(size_t)N_NODES * 2 * DIM_H]; // [h|comm]
__device__ __align__(16) __half g_qv16 [(size_t)N_NODES * NQV];  // [v|q|k], ld=320
__device__ __align__(16) __half g_t16  [(size_t)N_NODES * DIM_H];
__device__ float  g_bqkv[NQV];

// ---------------- prep: zero counts, convert x + weights to fp16 ----------------
__global__ void prep_kernel(const float* __restrict__ x,
                            const float* __restrict__ W_in,
                            const float* __restrict__ Wq, const float* __restrict__ bq,
                            const float* __restrict__ Wk, const float* __restrict__ bk,
                            const float* __restrict__ Wv, const float* __restrict__ bv,
                            const float* __restrict__ W1,
                            const float* __restrict__ W2) {
    int g = blockIdx.x * blockDim.x + threadIdx.x;
    int stride = gridDim.x * blockDim.x;
    for (int i = g; i < N_NODES * DIM_IN; i += stride) g_x16[i] = __float2half_rn(x[i]);
    for (int i = g; i < DIM_IN * DIM_H;  i += stride) g_win16[i] = __float2half_rn(W_in[i]);
    for (int i = g; i < 2 * DIM_H * DIM_H; i += stride) g_w116[i] = __float2half_rn(W1[i]);
    for (int i = g; i < DIM_H * DIM_OUT; i += stride) g_w216[i] = __float2half_rn(W2[i]);
    for (int i = g; i < DIM_H * NQV; i += stride) {
        int r = i / NQV, c = i % NQV;
        float w;
        if (c < 256)      w = Wv[r * 256 + c];
        else if (c < 288) w = Wq[r * 32 + (c - 256)];
        else              w = Wk[r * 32 + (c - 288)];
        g_wqkv16[i] = __float2half_rn(w);
    }
    for (int i = g; i < NQV; i += stride)
        g_bqkv[i] = (i < 256) ? bv[i] : (i < 288 ? bq[i - 256] : bk[i - 288]);
    for (int i = g; i < N_NODES; i += stride) g_cnt[i] = 0;
}

// ---------------- adjacency: append (dups deduped later in attn) ----------------
__global__ void insert_kernel(const int* __restrict__ ei) {
    int e = blockIdx.x * blockDim.x + threadIdx.x;
    if (e >= N_EDGES) return;
    int i = ei[e];
    int j = ei[N_EDGES + e];
    int pos = atomicAdd(&g_cnt[i], 1);
    if (pos < CAP) g_adj[i * CAP + pos] = j;
}

// ---------------- FP16 tensor-core GEMM, 8 warps, cp.async.ca 3-stage -----------
#define BN 64
#define BK 32
#define ASTR 40
#define BSTR 72
#define STAGES 3

__device__ __forceinline__ void ldsm_x4(uint32_t* r, uint32_t addr) {
    asm volatile("ldmatrix.sync.aligned.m8n8.x4.shared.b16 {%0,%1,%2,%3}, [%4];"
        : "=r"(r[0]), "=r"(r[1]), "=r"(r[2]), "=r"(r[3]) : "r"(addr));
}
__device__ __forceinline__ void ldsm_x4_t(uint32_t* r, uint32_t addr) {
    asm volatile("ldmatrix.sync.aligned.m8n8.x4.trans.shared.b16 {%0,%1,%2,%3}, [%4];"
        : "=r"(r[0]), "=r"(r[1]), "=r"(r[2]), "=r"(r[3]) : "r"(addr));
}
__device__ __forceinline__ void mma_f16(float* d, const uint32_t* a, const uint32_t* b) {
    asm volatile("mma.sync.aligned.m16n8k16.row.col.f32.f16.f16.f32 "
        "{%0,%1,%2,%3}, {%4,%5,%6,%7}, {%8,%9}, {%0,%1,%2,%3};"
        : "+f"(d[0]), "+f"(d[1]), "+f"(d[2]), "+f"(d[3])
        : "r"(a[0]), "r"(a[1]), "r"(a[2]), "r"(a[3]), "r"(b[0]), "r"(b[1]));
}
__device__ __forceinline__ void cp16(uint32_t dst, const void* src, int src_bytes) {
    asm volatile("cp.async.ca.shared.global [%0], [%1], 16, %2;"
        :: "r"(dst), "l"(src), "r"(src_bytes));
}
__device__ __forceinline__ void cp_commit() { asm volatile("cp.async.commit_group;"); }
template<int NN>
__device__ __forceinline__ void cp_wait() {
    asm volatile("cp.async.wait_group %0;" :: "n"(NN));
}

template<int TBM, int OUT16>
__global__ void __launch_bounds__(256, 3)
gemm_f16(const __half* __restrict__ A, int lda,
         const __half* __restrict__ B, int ldb,
         const float* __restrict__ bias,
         void* __restrict__ Cv, int ldc,
         int M, int K, int relu)
{
    constexpr int MI = TBM / 64;
    __shared__ __align__(16) __half As[STAGES][TBM * ASTR];
    __shared__ __align__(16) __half Bs[STAGES][BK * BSTR];

    const int tid  = threadIdx.x;
    const int lane = tid & 31;
    const int wid  = tid >> 5;
    const int wm   = wid & 3;
    const int wn   = wid >> 2;
    const int m0   = blockIdx.y * TBM;
    const int n0   = blockIdx.x * BN;

    const int a_row = tid >> 2;
    const int a_seg = (tid & 3) * 8;
    const int b_row = tid >> 3;
    const int b_seg = (tid & 7) * 8;

    const uint32_t as_base = (uint32_t)__cvta_generic_to_shared(&As[0][0]);
    const uint32_t bs_base = (uint32_t)__cvta_generic_to_shared(&Bs[0][0]);
    const int a_lane_h = (wm * (16 * MI) + (lane & 15)) * ASTR + ((lane >> 4) * 8);
    const int g3 = lane >> 3;
    const int b_lane_h = ((g3 & 1) * 8 + (lane & 7)) * BSTR + (g3 >> 1) * 8 + wn * 32;
    const uint32_t ABUF = TBM * ASTR * 2;
    const uint32_t BBUF = BK * BSTR * 2;

    const uint32_t aw = as_base + 2 * (a_row * ASTR + a_seg);
    const uint32_t bw = bs_base + 2 * (b_row * BSTR + b_seg);
    int a_valid[MI];
    const __half* a_src[MI];
    #pragma unroll
    for (int p = 0; p < MI; p++) {
        a_valid[p] = (m0 + p * 64 + a_row < M) ? 16 : 0;
        a_src[p] = A + (size_t)(m0 + p * 64 + a_row) * lda + a_seg;
    }
    const __half* b_src = B + (size_t)b_row * ldb + n0 + b_seg;

    float acc[MI][4][4];
    #pragma unroll
    for (int i = 0; i < MI; i++)
        #pragma unroll
        for (int j = 0; j < 4; j++)
            #pragma unroll
            for (int r = 0; r < 4; r++) acc[i][j][r] = 0.f;

    const int kt = K / BK;

    #pragma unroll
    for (int s = 0; s < STAGES - 1; s++) {
        if (s < kt) {
            int k0 = s * BK;
            #pragma unroll
            for (int p = 0; p < MI; p++)
                cp16(aw + s * ABUF + p * 64 * ASTR * 2, a_src[p] + k0, a_valid[p]);
            cp16(bw + s * BBUF, b_src + (size_t)k0 * ldb, 16);
        }
        cp_commit();
    }
    cp_wait<STAGES - 2>();
    __syncthreads();

    for (int t = 0; t < kt; t++) {
        const int cur = t % STAGES;
        #pragma unroll
        for (int ks = 0; ks < 2; ks++) {
            const int kb = ks * 16;
            uint32_t af[MI][4], bf[8];
            #pragma unroll
            for (int mi = 0; mi < MI; mi++)
                ldsm_x4(af[mi], as_base + cur * ABUF + 2 * (a_lane_h + mi * 16 * ASTR + kb));
            #pragma unroll
            for (int nh = 0; nh < 2; nh++)
                ldsm_x4_t(&bf[nh * 4], bs_base + cur * BBUF + 2 * (b_lane_h + kb * BSTR + nh * 16));
            #pragma unroll
            for (int mi = 0; mi < MI; mi++)
                #pragma unroll
                for (int nj = 0; nj < 4; nj++)
                    mma_f16(acc[mi][nj], af[mi], &bf[nj * 2]);
        }

        if (t + STAGES - 1 < kt) {
            int s = (t + STAGES - 1) % STAGES;
            int k0 = (t + STAGES - 1) * BK;
            #pragma unroll
            for (int p = 0; p < MI; p++)
                cp16(aw + s * ABUF + p * 64 * ASTR * 2, a_src[p] + k0, a_valid[p]);
            cp16(bw + s * BBUF, b_src + (size_t)k0 * ldb, 16);
        }
        cp_commit();
        cp_wait<STAGES - 2>();
        __syncthreads();
    }

    #pragma unroll
    for (int mi = 0; mi < MI; mi++) {
        int r0 = m0 + wm * (16 * MI) + mi * 16 + (lane >> 2);
        #pragma unroll
        for (int nj = 0; nj < 4; nj++) {
            int col = n0 + wn * 32 + nj * 8 + (lane & 3) * 2;
            float b0 = bias[col], b1 = bias[col + 1];
            float v0 = acc[mi][nj][0] + b0, v1 = acc[mi][nj][1] + b1;
            float v2 = acc[mi][nj][2] + b0, v3 = acc[mi][nj][3] + b1;
            if (relu) {
                v0 = fmaxf(v0, 0.f); v1 = fmaxf(v1, 0.f);
                v2 = fmaxf(v2, 0.f); v3 = fmaxf(v3, 0.f);
            }
            if (OUT16) {
                __half* C = (__half*)Cv;
                if (r0 < M)     *(__half2*)&C[(size_t)r0 * ldc + col]       = __floats2half2_rn(v0, v1);
                if (r0 + 8 < M) *(__half2*)&C[(size_t)(r0 + 8) * ldc + col] = __floats2half2_rn(v2, v3);
            } else {
                float* C = (float*)Cv;
                if (r0 < M)     *(float2*)&C[(size_t)r0 * ldc + col]       = make_float2(v0, v1);
                if (r0 + 8 < M) *(float2*)&C[(size_t)(r0 + 8) * ldc + col] = make_float2(v2, v3);
            }
        }
    }
}

// ---------------- sparse softmax attention: warp-per-row, no block barriers -----
// 8 warps/block, warp w owns row blockIdx.x*8+w. All sync is __syncwarp.
// Scores: 16-lane half-warp per neighbor (coalesced 64B k-row, width-16 shfl).
// Gather: full warp per neighbor (512B v-row via LDG.128), weight from smem.
// Scores are tiny (|sc| << 1): exp() is range-safe, no max-subtraction pass.
#define AROWS 8

__global__ void __launch_bounds__(256) attn_kernel() {
    const int lane = threadIdx.x & 31;
    const int wid  = threadIdx.x >> 5;
    const int row  = blockIdx.x * AROWS + wid;

    __shared__ unsigned s_bmp[AROWS][BMPW];
    __shared__ int      s_jw [AROWS][CAP];
    __shared__ float    s_ww [AROWS][CAP];

    if (row >= N_NODES) return;

    unsigned* bmp = s_bmp[wid];
    int*      jw  = s_jw[wid];
    float*    ww  = s_ww[wid];

    // clear bitmap (warp-local)
    for (int i = lane; i < BMPW; i += 32) bmp[i] = 0u;
    __syncwarp();

    int cnt = g_cnt[row];
    if (cnt > CAP) cnt = CAP;

    // phase 1: load adjacency, dedup via per-warp bitmap; ww = ok flag (0/1)
    for (int c = 0; c < cnt; c += 32) {
        int idx = c + lane;
        if (idx < cnt) {
            int j = g_adj[row * CAP + idx];
            jw[idx] = j;
            unsigned bit = 1u << (j & 31);
            unsigned old = atomicOr(&bmp[j >> 5], bit);
            ww[idx] = (old & bit) ? 0.f : 1.f;
        }
    }
    __syncwarp();

    // phase 2: scores. Half-warp (16 lanes) per neighbor, 2 neighbors/iteration.
    {
        const int hw  = lane >> 4;   // 0 or 1
        const int l16 = lane & 15;
        float2 q = __half22float2(
            *(const __half2*)(g_qv16 + (size_t)row * NQV + 256 + 2 * l16));
        for (int base = 0; base < cnt; base += 2) {
            int nb = base + hw;
            const bool valid = (nb < cnt);
            float d = 0.f;
            if (valid) {
                int j = jw[nb];
                float2 f = __half22float2(
                    *(const __half2*)(g_qv16 + (size_t)j * NQV + 288 + 2 * l16));
                d = q.x * f.x + q.y * f.y;
            }
            #pragma unroll
            for (int o = 8; o > 0; o >>= 1)
                d += __shfl_xor_sync(0xffffffffu, d, o, 16);
            if (valid && l16 == 0)
                ww[nb] = (ww[nb] != 0.f) ? __expf(d * 0.17677669529663687f) : 0.f;
        }
    }
    __syncwarp();

    // softmax denominator (warp reduce over <=128 entries)
    float e = 0.f;
    for (int idx = lane; idx < cnt; idx += 32) e += ww[idx];
    #pragma unroll
    for (int o = 16; o > 0; o >>= 1) e += __shfl_xor_sync(0xffffffffu, e, o);
    float inv = (e > 0.f) ? (1.f / e) : 0.f;
    for (int idx = lane; idx < cnt; idx += 32) ww[idx] *= inv;
    __syncwarp();

    // phase 3: v-gather, full warp per neighbor (512B row, LDG.128 per lane)
    float acc[8] = {};
    #pragma unroll 4
    for (int nb = 0; nb < cnt; nb++) {
        float w = ww[nb];
        uint4 d = *(const uint4*)(g_qv16 + (size_t)jw[nb] * NQV + 8 * lane);
        const uint32_t* dw = (const uint32_t*)&d;
        #pragma unroll
        for (int p = 0; p < 4; p++) {
            float2 f = __half22float2(*(const __half2*)&dw[p]);
            acc[2 * p]     += w * f.x;
            acc[2 * p + 1] += w * f.y;
        }
    }

    // store comm (8 halves per lane = one 16B store, coalesced 512B row)
    uint4 pk;
    uint32_t* pw = (uint32_t*)&pk;
    #pragma unroll
    for (int p = 0; p < 4; p++) {
        __half2 h = __floats2half2_rn(acc[2 * p], acc[2 * p + 1]);
        pw[p] = *(uint32_t*)&h;
    }
    *(uint4*)&g_comb16[(size_t)row * (2 * DIM_H) + DIM_H + 8 * lane] = pk;
}

// ---------------- launch ----------------------------------------------------------
extern "C" void kernel_launch(void* const* d_in, const int* in_sizes, int n_in,
                              void* d_out, int out_size) {
    const float* x    = (const float*)d_in[0];
    const int*   ei   = (const int*)  d_in[1];
    const float* W_in = (const float*)d_in[2];
    const float* b_in = (const float*)d_in[3];
    const float* Wq   = (const float*)d_in[4];
    const float* bq   = (const float*)d_in[5];
    const float* Wk   = (const float*)d_in[6];
    const float* bk   = (const float*)d_in[7];
    const float* Wv   = (const float*)d_in[8];
    const float* bv   = (const float*)d_in[9];
    const float* W1   = (const float*)d_in[10];
    const float* b1   = (const float*)d_in[11];
    const float* W2   = (const float*)d_in[12];
    const float* b2   = (const float*)d_in[13];
    float* out = (float*)d_out;

    __half *x16, *win16, *wqkv16, *w116, *w216, *comb16, *qv16, *t16;
    float *bqkv;
    cudaGetSymbolAddress((void**)&x16,    g_x16);
    cudaGetSymbolAddress((void**)&win16,  g_win16);
    cudaGetSymbolAddress((void**)&wqkv16, g_wqkv16);
    cudaGetSymbolAddress((void**)&w116,   g_w116);
    cudaGetSymbolAddress((void**)&w216,   g_w216);
    cudaGetSymbolAddress((void**)&comb16, g_comb16);
    cudaGetSymbolAddress((void**)&qv16,   g_qv16);
    cudaGetSymbolAddress((void**)&t16,    g_t16);
    cudaGetSymbolAddress((void**)&bqkv,   g_bqkv);

    const int MG128 = (N_NODES + 127) / 128;   // 79
    const int MG64  = (N_NODES + 63) / 64;     // 157

    prep_kernel  <<< 640, 256 >>> (x, W_in, Wq, bq, Wk, bk, Wv, bv, W1, W2);
    insert_kernel<<< (N_EDGES + 255) / 256, 256 >>> (ei);

    // h = x @ W_in + b_in  -> comb16[:, :256]
    gemm_f16<128,1><<< dim3(4, MG128), 256 >>>(x16, DIM_IN, win16, DIM_H, b_in,
                                               comb16, 2 * DIM_H, N_NODES, DIM_IN, 0);
    // [v|q|k] = h @ [Wv|Wq|Wk] + [bv|bq|bk]   (N=320)
    gemm_f16<128,1><<< dim3(5, MG128), 256 >>>(comb16, 2 * DIM_H, wqkv16, NQV, bqkv,
                                               qv16, NQV, N_NODES, DIM_H, 0);
    // sparse softmax attention -> comb16[:, 256:]
    attn_kernel<<< (N_NODES + AROWS - 1) / AROWS, 256 >>>();
    // t = relu(combined @ W1 + b1)
    gemm_f16<128,1><<< dim3(4, MG128), 256 >>>(comb16, 2 * DIM_H, w116, DIM_H, b1,
                                               t16, DIM_H, N_NODES, 2 * DIM_H, 1);
    // out = t @ W2 + b2  (fp32 out)
    gemm_f16<64,0><<< dim3(1, MG64), 256 >>>(t16, DIM_H, w216, DIM_OUT, b2,
                                             out, DIM_OUT, N_NODES, DIM_H, 0);
}